// round 10
// baseline (speedup 1.0000x reference)
#include <cuda_runtime.h>
#include <cuda_fp16.h>
#include <math.h>

// ---------------------------------------------------------------------------
// HyperKA 2-layer hyperbolic GCN.  N<=131072 nodes, D=64, E<=4M edges.
// Counting-sort edges by row each launch (graph-fork: prelude overlaps the
// sort on a second stream), then atomic-free warp-per-row gather with fp16
// feature rows (one 128B wavefront per edge).  All math fp32.
// ---------------------------------------------------------------------------

#define MAXN 131072
#define MAXE 4194304
#define D 64
#define FULLM 0xffffffffu

__device__ __half2 g_hh [(size_t)MAXN * 32];  // layer-1 SpMM input (dim l, dim l+32)
__device__ __half2 g_hh2[(size_t)MAXN * 32];  // layer-2 SpMM input
__device__ float   g_h1 [(size_t)MAXN * D];   // layer-1 output (residual), fp32
__device__ int     g_counts[MAXN];
__device__ int     g_off   [MAXN];
__device__ int     g_cursor[MAXN];
__device__ int     g_bsum [1024];
__device__ int     g_bscan[1024];
__device__ int2    g_edge [MAXE];             // .x = col, .y = val bits

#define EPS2    1e-12f        // EPS*EPS
#define PEPS    1e-5f         // PROJ_EPS
#define DEN_EPS 1e-6f

// ---- warp helpers (warp == one node, lane l owns dims l and l+32) ----------

__device__ __forceinline__ float wsum(float v) {
#pragma unroll
    for (int o = 16; o; o >>= 1) v += __shfl_xor_sync(FULLM, v, o);
    return v;
}

__device__ __forceinline__ void hproj(float& a, float& b) {
    float ss = wsum(a * a + b * b);
    float n  = sqrtf(fmaxf(ss, EPS2));
    float s  = fminf((1.0f - PEPS) / n, 1.0f);
    a *= s; b *= s;
}

__device__ __forceinline__ void expmap(float& a, float& b) {
    float ss = wsum(a * a + b * b);
    float n  = sqrtf(fmaxf(ss, EPS2));
    float s  = tanhf(n) / n;
    a *= s; b *= s;
}

__device__ __forceinline__ void logmap(float& a, float& b) {
    float ss = wsum(a * a + b * b);
    float n  = sqrtf(fmaxf(ss, EPS2));
    float s  = atanhf(fminf(n, 1.0f - PEPS)) / n;
    a *= s; b *= s;
}

// x <- mobius_add(x, y)
__device__ __forceinline__ void mobius(float& xa, float& xb, float ya, float yb) {
    float x2 = wsum(xa * xa + xb * xb);
    float y2 = wsum(ya * ya + yb * yb);
    float xy = wsum(xa * ya + xb * yb);
    float c1  = 1.0f + 2.0f * xy + y2;
    float c2  = 1.0f - x2;
    float den = fmaxf(1.0f + 2.0f * xy + x2 * y2, DEN_EPS);
    float inv = 1.0f / den;
    xa = (c1 * xa + c2 * ya) * inv;
    xb = (c1 * xb + c2 * yb) * inv;
}

// o = v @ W  (W in smem, row-major 64x64)
__device__ __forceinline__ void matvec(float a, float b, const float* Ws, int lane,
                                       float& o0, float& o1) {
    o0 = 0.0f; o1 = 0.0f;
#pragma unroll
    for (int k = 0; k < 32; k++) {
        float t = __shfl_sync(FULLM, a, k);
        o0 = fmaf(t, Ws[k * 64 + lane],      o0);
        o1 = fmaf(t, Ws[k * 64 + lane + 32], o1);
    }
#pragma unroll
    for (int k = 0; k < 32; k++) {
        float t = __shfl_sync(FULLM, b, k);
        o0 = fmaf(t, Ws[(k + 32) * 64 + lane],      o0);
        o1 = fmaf(t, Ws[(k + 32) * 64 + lane + 32], o1);
    }
}

// warp-per-row gather: (a0,a1) = sum over row's edges of val * src[col]
// src row = 32 half2 (128B); lane l reads entry l -> one wavefront per edge.
// 8-wide unrolled broadcast loop for MLP=8.
__device__ __forceinline__ void gather_row(const __half2* __restrict__ src,
                                           int node, int lane,
                                           float& a0, float& a1) {
    int start = g_off[node];
    int deg   = g_counts[node];
    a0 = 0.0f; a1 = 0.0f;
    for (int j0 = 0; j0 < deg; j0 += 32) {
        int rem = deg - j0;
        int m = rem < 32 ? rem : 32;
        int2 ev = make_int2(0, 0);
        if (lane < m) ev = g_edge[start + j0 + lane];
        int j = 0;
        for (; j + 8 <= m; j += 8) {
            int   c[8]; float v[8]; float2 f[8];
#pragma unroll
            for (int q = 0; q < 8; q++) {
                c[q] = __shfl_sync(FULLM, ev.x, j + q);
                v[q] = __int_as_float(__shfl_sync(FULLM, ev.y, j + q));
            }
#pragma unroll
            for (int q = 0; q < 8; q++)
                f[q] = __half22float2(src[(size_t)c[q] * 32 + lane]);
#pragma unroll
            for (int q = 0; q < 8; q++) {
                a0 = fmaf(v[q], f[q].x, a0);
                a1 = fmaf(v[q], f[q].y, a1);
            }
        }
        for (; j < m; j++) {
            int   cc = __shfl_sync(FULLM, ev.x, j);
            float vv = __int_as_float(__shfl_sync(FULLM, ev.y, j));
            float2 f = __half22float2(src[(size_t)cc * 32 + lane]);
            a0 = fmaf(vv, f.x, a0);
            a1 = fmaf(vv, f.y, a1);
        }
    }
}

// ---------------------------------------------------------------------------
// K1 (stream B): g_hh = half2( log_map(hyp_proj(x)) @ W1 )
// ---------------------------------------------------------------------------
__global__ void k_prelude(const float* __restrict__ x, const float* __restrict__ W, int N) {
    __shared__ float Ws[64 * 64];
    for (int i = threadIdx.x; i < 64 * 64; i += blockDim.x) Ws[i] = W[i];
    __syncthreads();

    int node = (int)((blockIdx.x * blockDim.x + threadIdx.x) >> 5);
    int lane = threadIdx.x & 31;
    if (node >= N) return;
    size_t base = (size_t)node * D;

    float a = x[base + lane], b = x[base + lane + 32];
    hproj(a, b);
    logmap(a, b);

    float o0, o1;
    matvec(a, b, Ws, lane, o0, o1);
    g_hh[(size_t)node * 32 + lane] = __floats2half2_rn(o0, o1);
}

// ---------------------------------------------------------------------------
// counting sort of edges by row (main stream)
// ---------------------------------------------------------------------------
__global__ void k_zero(int N) {
    int i = blockIdx.x * blockDim.x + threadIdx.x;
    if (i < N) g_counts[i] = 0;
}

__global__ void k_hist(const int* __restrict__ rows, int E) {
    int e = (blockIdx.x * blockDim.x + threadIdx.x) * 4;
    if (e + 4 <= E) {
        int4 r = *reinterpret_cast<const int4*>(rows + e);
        atomicAdd(&g_counts[r.x], 1);
        atomicAdd(&g_counts[r.y], 1);
        atomicAdd(&g_counts[r.z], 1);
        atomicAdd(&g_counts[r.w], 1);
    } else {
        for (int k = e; k < E; k++) atomicAdd(&g_counts[rows[k]], 1);
    }
}

__global__ void k_scan_block(int N) {
    __shared__ int ws[32];
    int tid = threadIdx.x, lane = tid & 31, wid = tid >> 5;
    int i = blockIdx.x * 1024 + tid;
    int v = (i < N) ? g_counts[i] : 0;
    int x = v;
#pragma unroll
    for (int o = 1; o < 32; o <<= 1) {
        int t = __shfl_up_sync(FULLM, x, o);
        if (lane >= o) x += t;
    }
    if (lane == 31) ws[wid] = x;
    __syncthreads();
    if (wid == 0) {
        int y = ws[lane];
#pragma unroll
        for (int o = 1; o < 32; o <<= 1) {
            int t = __shfl_up_sync(FULLM, y, o);
            if (lane >= o) y += t;
        }
        ws[lane] = y;
    }
    __syncthreads();
    int wpre = (wid == 0) ? 0 : ws[wid - 1];
    if (i < N) g_off[i] = wpre + x - v;               // exclusive within block
    if (tid == 1023) g_bsum[blockIdx.x] = wpre + x;   // block total
}

__global__ void k_scan_top(int nb) {
    __shared__ int ws[32];
    int tid = threadIdx.x, lane = tid & 31, wid = tid >> 5;
    int v = (tid < nb) ? g_bsum[tid] : 0;
    int x = v;
#pragma unroll
    for (int o = 1; o < 32; o <<= 1) {
        int t = __shfl_up_sync(FULLM, x, o);
        if (lane >= o) x += t;
    }
    if (lane == 31) ws[wid] = x;
    __syncthreads();
    if (wid == 0) {
        int y = ws[lane];
#pragma unroll
        for (int o = 1; o < 32; o <<= 1) {
            int t = __shfl_up_sync(FULLM, y, o);
            if (lane >= o) y += t;
        }
        ws[lane] = y;
    }
    __syncthreads();
    int wpre = (wid == 0) ? 0 : ws[wid - 1];
    if (tid < nb) g_bscan[tid] = wpre + x - v;        // exclusive scan of block sums
}

__global__ void k_scan_add(int N) {
    int i = blockIdx.x * blockDim.x + threadIdx.x;
    if (i >= N) return;
    int o = g_off[i] + g_bscan[i >> 10];
    g_off[i] = o;
    g_cursor[i] = o;
}

__global__ void k_reorder(const int* __restrict__ rows, const int* __restrict__ cols,
                          const float* __restrict__ vals, int E) {
    int e = (blockIdx.x * blockDim.x + threadIdx.x) * 4;
    if (e + 4 <= E) {
        int4   r = *reinterpret_cast<const int4*>(rows + e);
        int4   c = *reinterpret_cast<const int4*>(cols + e);
        float4 v = *reinterpret_cast<const float4*>(vals + e);
        int p0 = atomicAdd(&g_cursor[r.x], 1);
        int p1 = atomicAdd(&g_cursor[r.y], 1);
        int p2 = atomicAdd(&g_cursor[r.z], 1);
        int p3 = atomicAdd(&g_cursor[r.w], 1);
        g_edge[p0] = make_int2(c.x, __float_as_int(v.x));
        g_edge[p1] = make_int2(c.y, __float_as_int(v.y));
        g_edge[p2] = make_int2(c.z, __float_as_int(v.z));
        g_edge[p3] = make_int2(c.w, __float_as_int(v.w));
    } else {
        for (int k = e; k < E; k++) {
            int p = atomicAdd(&g_cursor[rows[k]], 1);
            g_edge[p] = make_int2(cols[k], __float_as_int(vals[k]));
        }
    }
}

// ---------------------------------------------------------------------------
// K-layer1: gather(g_hh) -> epilogue+act -> residual(e0) -> g_h1,
//           then log_map + @W2 -> g_hh2
// ---------------------------------------------------------------------------
__global__ void k_layer1(const float* __restrict__ x, const float* __restrict__ bias,
                         const float* __restrict__ W2, int N) {
    __shared__ float Ws[64 * 64];
    for (int i = threadIdx.x; i < 64 * 64; i += blockDim.x) Ws[i] = W2[i];
    __syncthreads();

    int node = (int)((blockIdx.x * blockDim.x + threadIdx.x) >> 5);
    int lane = threadIdx.x & 31;
    if (node >= N) return;
    size_t base = (size_t)node * D;

    float oa, ob;
    gather_row(g_hh, node, lane, oa, ob);

    // bias in hyperbolic space
    float ba = bias[lane], bb = bias[lane + 32];
    expmap(ba, bb); hproj(ba, bb);

    expmap(oa, ob); hproj(oa, ob);
    mobius(oa, ob, ba, bb); hproj(oa, ob);
    // activation: hyp_proj(exp_map(tanh(log_map(out))))
    logmap(oa, ob);
    oa = tanhf(oa); ob = tanhf(ob);
    expmap(oa, ob); hproj(oa, ob);

    // residual with e0 = hyp_proj(x)
    float ea = x[base + lane], eb = x[base + lane + 32];
    hproj(ea, eb);
    mobius(oa, ob, ea, eb); hproj(oa, ob);

    g_h1[base + lane] = oa;
    g_h1[base + lane + 32] = ob;

    // layer-2 prelude
    logmap(oa, ob);
    float o0, o1;
    matvec(oa, ob, Ws, lane, o0, o1);
    g_hh2[(size_t)node * 32 + lane] = __floats2half2_rn(o0, o1);
}

// ---------------------------------------------------------------------------
// K-layer2: gather(g_hh2) -> epilogue (no act) -> residual(g_h1) -> out
// ---------------------------------------------------------------------------
__global__ void k_layer2(const float* __restrict__ bias, float* __restrict__ out, int N) {
    int node = (int)((blockIdx.x * blockDim.x + threadIdx.x) >> 5);
    int lane = threadIdx.x & 31;
    if (node >= N) return;
    size_t base = (size_t)node * D;

    float oa, ob;
    gather_row(g_hh2, node, lane, oa, ob);

    float ba = bias[lane], bb = bias[lane + 32];
    expmap(ba, bb); hproj(ba, bb);

    expmap(oa, ob); hproj(oa, ob);
    mobius(oa, ob, ba, bb); hproj(oa, ob);

    float ra = g_h1[base + lane], rb = g_h1[base + lane + 32];
    mobius(oa, ob, ra, rb); hproj(oa, ob);

    out[base + lane] = oa;
    out[base + lane + 32] = ob;
}

// ---------------------------------------------------------------------------
extern "C" void kernel_launch(void* const* d_in, const int* in_sizes, int n_in,
                              void* d_out, int out_size) {
    const float* x    = (const float*)d_in[0];
    const float* vals = (const float*)d_in[1];
    const float* W1   = (const float*)d_in[2];
    const float* b1   = (const float*)d_in[3];
    const float* W2   = (const float*)d_in[4];
    const float* b2   = (const float*)d_in[5];
    const int*   rows = (const int*)d_in[6];
    const int*   cols = (const int*)d_in[7];

    int N = in_sizes[0] / D;
    int E = in_sizes[1];

    int nodeBlocks  = (N + 7) / 8;            // 8 warps (nodes) per 256-thread block
    int edge4Blocks = (E / 4 + 256) / 256;    // 4 edges per thread (covers tail)
    int nb          = (N + 1023) / 1024;      // scan blocks (<= 1024)

    // Fork: prelude (depends only on x, W1) runs concurrently with the
    // edge counting-sort chain.  Works both eagerly and under graph capture.
    cudaStream_t s2;
    cudaStreamCreateWithFlags(&s2, cudaStreamNonBlocking);
    cudaEvent_t e0, e1;
    cudaEventCreateWithFlags(&e0, cudaEventDisableTiming);
    cudaEventCreateWithFlags(&e1, cudaEventDisableTiming);

    cudaEventRecord(e0, 0);
    cudaStreamWaitEvent(s2, e0, 0);
    k_prelude<<<nodeBlocks, 256, 0, s2>>>(x, W1, N);
    cudaEventRecord(e1, s2);

    k_zero      <<<(N + 255) / 256, 256>>>(N);
    k_hist      <<<edge4Blocks, 256>>>(rows, E);
    k_scan_block<<<nb, 1024>>>(N);
    k_scan_top  <<<1, 1024>>>(nb);
    k_scan_add  <<<(N + 255) / 256, 256>>>(N);
    k_reorder   <<<edge4Blocks, 256>>>(rows, cols, vals, E);

    cudaStreamWaitEvent(0, e1, 0);
    k_layer1    <<<nodeBlocks, 256>>>(x, b1, W2, N);
    k_layer2    <<<nodeBlocks, 256>>>(b2, (float*)d_out, N);

    cudaEventDestroy(e0);
    cudaEventDestroy(e1);
    cudaStreamDestroy(s2);
}

// round 11
// speedup vs baseline: 1.0322x; 1.0322x over previous
#include <cuda_runtime.h>
#include <cuda_fp16.h>
#include <math.h>

// ---------------------------------------------------------------------------
// HyperKA 2-layer hyperbolic GCN.  N<=131072 nodes, D=64, E<=4M edges.
// Counting-sort edges by row each launch, then atomic-free warp-per-row
// gather with fp16 feature rows (one 128B wavefront per edge).  Math fp32.
// Sort uses g_off as its own cursor (no scan_add kernel, no cursor array).
// ---------------------------------------------------------------------------

#define MAXN 131072
#define MAXE 4194304
#define D 64
#define FULLM 0xffffffffu

__device__ __half2 g_hh [(size_t)MAXN * 32];  // layer-1 SpMM input (dim l, dim l+32)
__device__ __half2 g_hh2[(size_t)MAXN * 32];  // layer-2 SpMM input
__device__ float   g_h1 [(size_t)MAXN * D];   // layer-1 output (residual), fp32
__device__ int     g_counts[MAXN];
__device__ int     g_off   [MAXN];            // block-local excl. scan; cursor during reorder
__device__ int     g_bsum [1024];
__device__ int     g_bscan[1024];             // exclusive scan of 1024-blocks
__device__ int2    g_edge [MAXE];             // .x = col, .y = val bits

#define EPS2    1e-12f        // EPS*EPS
#define PEPS    1e-5f         // PROJ_EPS
#define DEN_EPS 1e-6f

// ---- warp helpers (warp == one node, lane l owns dims l and l+32) ----------

__device__ __forceinline__ float wsum(float v) {
#pragma unroll
    for (int o = 16; o; o >>= 1) v += __shfl_xor_sync(FULLM, v, o);
    return v;
}

__device__ __forceinline__ void hproj(float& a, float& b) {
    float ss = wsum(a * a + b * b);
    float n  = sqrtf(fmaxf(ss, EPS2));
    float s  = fminf((1.0f - PEPS) / n, 1.0f);
    a *= s; b *= s;
}

__device__ __forceinline__ void expmap(float& a, float& b) {
    float ss = wsum(a * a + b * b);
    float n  = sqrtf(fmaxf(ss, EPS2));
    float s  = tanhf(n) / n;
    a *= s; b *= s;
}

__device__ __forceinline__ void logmap(float& a, float& b) {
    float ss = wsum(a * a + b * b);
    float n  = sqrtf(fmaxf(ss, EPS2));
    float s  = atanhf(fminf(n, 1.0f - PEPS)) / n;
    a *= s; b *= s;
}

// x <- mobius_add(x, y)
__device__ __forceinline__ void mobius(float& xa, float& xb, float ya, float yb) {
    float x2 = wsum(xa * xa + xb * xb);
    float y2 = wsum(ya * ya + yb * yb);
    float xy = wsum(xa * ya + xb * yb);
    float c1  = 1.0f + 2.0f * xy + y2;
    float c2  = 1.0f - x2;
    float den = fmaxf(1.0f + 2.0f * xy + x2 * y2, DEN_EPS);
    float inv = 1.0f / den;
    xa = (c1 * xa + c2 * ya) * inv;
    xb = (c1 * xb + c2 * yb) * inv;
}

// o = v @ W  (W in smem, row-major 64x64)
__device__ __forceinline__ void matvec(float a, float b, const float* Ws, int lane,
                                       float& o0, float& o1) {
    o0 = 0.0f; o1 = 0.0f;
#pragma unroll
    for (int k = 0; k < 32; k++) {
        float t = __shfl_sync(FULLM, a, k);
        o0 = fmaf(t, Ws[k * 64 + lane],      o0);
        o1 = fmaf(t, Ws[k * 64 + lane + 32], o1);
    }
#pragma unroll
    for (int k = 0; k < 32; k++) {
        float t = __shfl_sync(FULLM, b, k);
        o0 = fmaf(t, Ws[(k + 32) * 64 + lane],      o0);
        o1 = fmaf(t, Ws[(k + 32) * 64 + lane + 32], o1);
    }
}

// warp-per-row gather: (a0,a1) = sum over row's edges of val * src[col]
// src row = 32 half2 (128B); lane l reads entry l -> one wavefront per edge.
__device__ __forceinline__ void gather_row(const __half2* __restrict__ src,
                                           int node, int lane,
                                           float& a0, float& a1) {
    int deg   = g_counts[node];
    // post-reorder g_off[node] = local_off + deg; global start = +bscan - deg
    int start = g_off[node] + g_bscan[node >> 10] - deg;
    a0 = 0.0f; a1 = 0.0f;
    for (int j0 = 0; j0 < deg; j0 += 32) {
        int rem = deg - j0;
        int m = rem < 32 ? rem : 32;
        int2 ev = make_int2(0, 0);
        if (lane < m) ev = __ldcs(&g_edge[start + j0 + lane]);   // streaming: keep L1 for src
        int j = 0;
        for (; j + 4 <= m; j += 4) {
            int   c0 = __shfl_sync(FULLM, ev.x, j);
            int   c1 = __shfl_sync(FULLM, ev.x, j + 1);
            int   c2 = __shfl_sync(FULLM, ev.x, j + 2);
            int   c3 = __shfl_sync(FULLM, ev.x, j + 3);
            float v0 = __int_as_float(__shfl_sync(FULLM, ev.y, j));
            float v1 = __int_as_float(__shfl_sync(FULLM, ev.y, j + 1));
            float v2 = __int_as_float(__shfl_sync(FULLM, ev.y, j + 2));
            float v3 = __int_as_float(__shfl_sync(FULLM, ev.y, j + 3));
            float2 f0 = __half22float2(src[(size_t)c0 * 32 + lane]);
            float2 f1 = __half22float2(src[(size_t)c1 * 32 + lane]);
            float2 f2 = __half22float2(src[(size_t)c2 * 32 + lane]);
            float2 f3 = __half22float2(src[(size_t)c3 * 32 + lane]);
            a0 = fmaf(v0, f0.x, a0); a1 = fmaf(v0, f0.y, a1);
            a0 = fmaf(v1, f1.x, a0); a1 = fmaf(v1, f1.y, a1);
            a0 = fmaf(v2, f2.x, a0); a1 = fmaf(v2, f2.y, a1);
            a0 = fmaf(v3, f3.x, a0); a1 = fmaf(v3, f3.y, a1);
        }
        for (; j < m; j++) {
            int   cc = __shfl_sync(FULLM, ev.x, j);
            float vv = __int_as_float(__shfl_sync(FULLM, ev.y, j));
            float2 f = __half22float2(src[(size_t)cc * 32 + lane]);
            a0 = fmaf(vv, f.x, a0);
            a1 = fmaf(vv, f.y, a1);
        }
    }
}

// ---------------------------------------------------------------------------
// K1: g_hh = half2( log_map(hyp_proj(x)) @ W1 ) ; zero g_counts
// ---------------------------------------------------------------------------
__global__ void k_prelude(const float* __restrict__ x, const float* __restrict__ W, int N) {
    __shared__ float Ws[64 * 64];
    for (int i = threadIdx.x; i < 64 * 64; i += blockDim.x) Ws[i] = W[i];
    __syncthreads();

    int node = (int)((blockIdx.x * blockDim.x + threadIdx.x) >> 5);
    int lane = threadIdx.x & 31;
    if (node >= N) return;
    size_t base = (size_t)node * D;

    if (lane == 0) g_counts[node] = 0;

    float a = x[base + lane], b = x[base + lane + 32];
    hproj(a, b);
    logmap(a, b);

    float o0, o1;
    matvec(a, b, Ws, lane, o0, o1);
    g_hh[(size_t)node * 32 + lane] = __floats2half2_rn(o0, o1);
}

// ---------------------------------------------------------------------------
// counting sort of edges by row
// ---------------------------------------------------------------------------
__global__ void k_hist(const int* __restrict__ rows, int E) {
    int e = (blockIdx.x * blockDim.x + threadIdx.x) * 4;
    if (e + 4 <= E) {
        int4 r = *reinterpret_cast<const int4*>(rows + e);
        atomicAdd(&g_counts[r.x], 1);
        atomicAdd(&g_counts[r.y], 1);
        atomicAdd(&g_counts[r.z], 1);
        atomicAdd(&g_counts[r.w], 1);
    } else {
        for (int k = e; k < E; k++) atomicAdd(&g_counts[rows[k]], 1);
    }
}

__global__ void k_scan_block(int N) {
    __shared__ int ws[32];
    int tid = threadIdx.x, lane = tid & 31, wid = tid >> 5;
    int i = blockIdx.x * 1024 + tid;
    int v = (i < N) ? g_counts[i] : 0;
    int x = v;
#pragma unroll
    for (int o = 1; o < 32; o <<= 1) {
        int t = __shfl_up_sync(FULLM, x, o);
        if (lane >= o) x += t;
    }
    if (lane == 31) ws[wid] = x;
    __syncthreads();
    if (wid == 0) {
        int y = ws[lane];
#pragma unroll
        for (int o = 1; o < 32; o <<= 1) {
            int t = __shfl_up_sync(FULLM, y, o);
            if (lane >= o) y += t;
        }
        ws[lane] = y;
    }
    __syncthreads();
    int wpre = (wid == 0) ? 0 : ws[wid - 1];
    if (i < N) g_off[i] = wpre + x - v;               // exclusive within block
    if (tid == 1023) g_bsum[blockIdx.x] = wpre + x;   // block total
}

__global__ void k_scan_top(int nb) {
    __shared__ int ws[32];
    int tid = threadIdx.x, lane = tid & 31, wid = tid >> 5;
    int v = (tid < nb) ? g_bsum[tid] : 0;
    int x = v;
#pragma unroll
    for (int o = 1; o < 32; o <<= 1) {
        int t = __shfl_up_sync(FULLM, x, o);
        if (lane >= o) x += t;
    }
    if (lane == 31) ws[wid] = x;
    __syncthreads();
    if (wid == 0) {
        int y = ws[lane];
#pragma unroll
        for (int o = 1; o < 32; o <<= 1) {
            int t = __shfl_up_sync(FULLM, y, o);
            if (lane >= o) y += t;
        }
        ws[lane] = y;
    }
    __syncthreads();
    int wpre = (wid == 0) ? 0 : ws[wid - 1];
    if (tid < nb) g_bscan[tid] = wpre + x - v;        // exclusive scan of block sums
}

// reorder: position = (atomic bump of block-local g_off) + block base from g_bscan
__global__ void k_reorder(const int* __restrict__ rows, const int* __restrict__ cols,
                          const float* __restrict__ vals, int E) {
    int e = (blockIdx.x * blockDim.x + threadIdx.x) * 4;
    if (e + 4 <= E) {
        int4   r = *reinterpret_cast<const int4*>(rows + e);
        int4   c = *reinterpret_cast<const int4*>(cols + e);
        float4 v = *reinterpret_cast<const float4*>(vals + e);
        int p0 = atomicAdd(&g_off[r.x], 1) + g_bscan[r.x >> 10];
        int p1 = atomicAdd(&g_off[r.y], 1) + g_bscan[r.y >> 10];
        int p2 = atomicAdd(&g_off[r.z], 1) + g_bscan[r.z >> 10];
        int p3 = atomicAdd(&g_off[r.w], 1) + g_bscan[r.w >> 10];
        g_edge[p0] = make_int2(c.x, __float_as_int(v.x));
        g_edge[p1] = make_int2(c.y, __float_as_int(v.y));
        g_edge[p2] = make_int2(c.z, __float_as_int(v.z));
        g_edge[p3] = make_int2(c.w, __float_as_int(v.w));
    } else {
        for (int k = e; k < E; k++) {
            int r = rows[k];
            int p = atomicAdd(&g_off[r], 1) + g_bscan[r >> 10];
            g_edge[p] = make_int2(cols[k], __float_as_int(vals[k]));
        }
    }
}

// ---------------------------------------------------------------------------
// K-layer1: gather(g_hh) -> epilogue+act -> residual(e0) -> g_h1,
//           then log_map + @W2 -> g_hh2
// ---------------------------------------------------------------------------
__global__ void k_layer1(const float* __restrict__ x, const float* __restrict__ bias,
                         const float* __restrict__ W2, int N) {
    __shared__ float Ws[64 * 64];
    for (int i = threadIdx.x; i < 64 * 64; i += blockDim.x) Ws[i] = W2[i];
    __syncthreads();

    int node = (int)((blockIdx.x * blockDim.x + threadIdx.x) >> 5);
    int lane = threadIdx.x & 31;
    if (node >= N) return;
    size_t base = (size_t)node * D;

    float oa, ob;
    gather_row(g_hh, node, lane, oa, ob);

    // bias in hyperbolic space
    float ba = bias[lane], bb = bias[lane + 32];
    expmap(ba, bb); hproj(ba, bb);

    expmap(oa, ob); hproj(oa, ob);
    mobius(oa, ob, ba, bb); hproj(oa, ob);
    // activation: hyp_proj(exp_map(tanh(log_map(out))))
    logmap(oa, ob);
    oa = tanhf(oa); ob = tanhf(ob);
    expmap(oa, ob); hproj(oa, ob);

    // residual with e0 = hyp_proj(x)
    float ea = x[base + lane], eb = x[base + lane + 32];
    hproj(ea, eb);
    mobius(oa, ob, ea, eb); hproj(oa, ob);

    g_h1[base + lane] = oa;
    g_h1[base + lane + 32] = ob;

    // layer-2 prelude
    logmap(oa, ob);
    float o0, o1;
    matvec(oa, ob, Ws, lane, o0, o1);
    g_hh2[(size_t)node * 32 + lane] = __floats2half2_rn(o0, o1);
}

// ---------------------------------------------------------------------------
// K-layer2: gather(g_hh2) -> epilogue (no act) -> residual(g_h1) -> out
// ---------------------------------------------------------------------------
__global__ void k_layer2(const float* __restrict__ bias, float* __restrict__ out, int N) {
    int node = (int)((blockIdx.x * blockDim.x + threadIdx.x) >> 5);
    int lane = threadIdx.x & 31;
    if (node >= N) return;
    size_t base = (size_t)node * D;

    float oa, ob;
    gather_row(g_hh2, node, lane, oa, ob);

    float ba = bias[lane], bb = bias[lane + 32];
    expmap(ba, bb); hproj(ba, bb);

    expmap(oa, ob); hproj(oa, ob);
    mobius(oa, ob, ba, bb); hproj(oa, ob);

    float ra = g_h1[base + lane], rb = g_h1[base + lane + 32];
    mobius(oa, ob, ra, rb); hproj(oa, ob);

    out[base + lane] = oa;
    out[base + lane + 32] = ob;
}

// ---------------------------------------------------------------------------
extern "C" void kernel_launch(void* const* d_in, const int* in_sizes, int n_in,
                              void* d_out, int out_size) {
    const float* x    = (const float*)d_in[0];
    const float* vals = (const float*)d_in[1];
    const float* W1   = (const float*)d_in[2];
    const float* b1   = (const float*)d_in[3];
    const float* W2   = (const float*)d_in[4];
    const float* b2   = (const float*)d_in[5];
    const int*   rows = (const int*)d_in[6];
    const int*   cols = (const int*)d_in[7];

    int N = in_sizes[0] / D;
    int E = in_sizes[1];

    int nodeBlocks  = (N + 7) / 8;            // 8 warps (nodes) per 256-thread block
    int edge4Blocks = (E / 4 + 256) / 256;    // 4 edges per thread (covers tail)
    int nb          = (N + 1023) / 1024;      // scan blocks (<= 1024)

    k_prelude   <<<nodeBlocks, 256>>>(x, W1, N);
    k_hist      <<<edge4Blocks, 256>>>(rows, E);
    k_scan_block<<<nb, 1024>>>(N);
    k_scan_top  <<<1, 1024>>>(nb);
    k_reorder   <<<edge4Blocks, 256>>>(rows, cols, vals, E);
    k_layer1    <<<nodeBlocks, 256>>>(x, b1, W2, N);
    k_layer2    <<<nodeBlocks, 256>>>(b2, (float*)d_out, N);
}

// round 12
// speedup vs baseline: 1.1197x; 1.0847x over previous
#include <cuda_runtime.h>
#include <cuda_fp16.h>
#include <math.h>

// ---------------------------------------------------------------------------
// HyperKA 2-layer hyperbolic GCN.  N<=131072 nodes, D=64, E<=4M edges.
// Counting-sort edges by row each launch, then atomic-free warp-per-row
// gather with fp16 feature rows (one 128B wavefront per edge).  Math fp32.
// Gather broadcasts edges via per-warp smem staging (no shfl chains).
// ---------------------------------------------------------------------------

#define MAXN 131072
#define MAXE 4194304
#define D 64
#define FULLM 0xffffffffu

__device__ __half2 g_hh [(size_t)MAXN * 32];  // layer-1 SpMM input (dim l, dim l+32)
__device__ __half2 g_hh2[(size_t)MAXN * 32];  // layer-2 SpMM input
__device__ float   g_h1 [(size_t)MAXN * D];   // layer-1 output (residual), fp32
__device__ int     g_counts[MAXN];
__device__ int     g_off   [MAXN];            // block-local excl. scan; cursor during reorder
__device__ int     g_bsum [1024];
__device__ int     g_bscan[1024];             // exclusive scan of 1024-blocks
__device__ int2    g_edge [MAXE];             // .x = col, .y = val bits

#define EPS2    1e-12f        // EPS*EPS
#define PEPS    1e-5f         // PROJ_EPS
#define DEN_EPS 1e-6f

// ---- warp helpers (warp == one node, lane l owns dims l and l+32) ----------

__device__ __forceinline__ float wsum(float v) {
#pragma unroll
    for (int o = 16; o; o >>= 1) v += __shfl_xor_sync(FULLM, v, o);
    return v;
}

__device__ __forceinline__ void hproj(float& a, float& b) {
    float ss = wsum(a * a + b * b);
    float n  = sqrtf(fmaxf(ss, EPS2));
    float s  = fminf((1.0f - PEPS) / n, 1.0f);
    a *= s; b *= s;
}

__device__ __forceinline__ void expmap(float& a, float& b) {
    float ss = wsum(a * a + b * b);
    float n  = sqrtf(fmaxf(ss, EPS2));
    float s  = tanhf(n) / n;
    a *= s; b *= s;
}

__device__ __forceinline__ void logmap(float& a, float& b) {
    float ss = wsum(a * a + b * b);
    float n  = sqrtf(fmaxf(ss, EPS2));
    float s  = atanhf(fminf(n, 1.0f - PEPS)) / n;
    a *= s; b *= s;
}

// x <- mobius_add(x, y)
__device__ __forceinline__ void mobius(float& xa, float& xb, float ya, float yb) {
    float x2 = wsum(xa * xa + xb * xb);
    float y2 = wsum(ya * ya + yb * yb);
    float xy = wsum(xa * ya + xb * yb);
    float c1  = 1.0f + 2.0f * xy + y2;
    float c2  = 1.0f - x2;
    float den = fmaxf(1.0f + 2.0f * xy + x2 * y2, DEN_EPS);
    float inv = 1.0f / den;
    xa = (c1 * xa + c2 * ya) * inv;
    xb = (c1 * xb + c2 * yb) * inv;
}

// o = v @ W  (W in smem, row-major 64x64)
__device__ __forceinline__ void matvec(float a, float b, const float* Ws, int lane,
                                       float& o0, float& o1) {
    o0 = 0.0f; o1 = 0.0f;
#pragma unroll
    for (int k = 0; k < 32; k++) {
        float t = __shfl_sync(FULLM, a, k);
        o0 = fmaf(t, Ws[k * 64 + lane],      o0);
        o1 = fmaf(t, Ws[k * 64 + lane + 32], o1);
    }
#pragma unroll
    for (int k = 0; k < 32; k++) {
        float t = __shfl_sync(FULLM, b, k);
        o0 = fmaf(t, Ws[(k + 32) * 64 + lane],      o0);
        o1 = fmaf(t, Ws[(k + 32) * 64 + lane + 32], o1);
    }
}

// warp-per-row gather: (a0,a1) = sum over row's edges of val * src[col].
// Edges staged to per-warp smem, broadcast via LDS (no shfl chains);
// feature loads unrolled x8 for MLP=8.
__device__ __forceinline__ void gather_row(const __half2* __restrict__ src,
                                           int2* __restrict__ s_e,   // per-warp [32]
                                           int node, int lane,
                                           float& a0, float& a1) {
    int deg   = g_counts[node];
    // post-reorder g_off[node] = local_off + deg; global start = +bscan - deg
    int start = g_off[node] + g_bscan[node >> 10] - deg;
    a0 = 0.0f; a1 = 0.0f;
    const __half2* srcl = src + lane;
    for (int j0 = 0; j0 < deg; j0 += 32) {
        int rem = deg - j0;
        int m = rem < 32 ? rem : 32;
        if (lane < m) s_e[lane] = g_edge[start + j0 + lane];
        __syncwarp();
        int j = 0;
        for (; j + 8 <= m; j += 8) {
            float v[8]; float2 f[8];
#pragma unroll
            for (int q = 0; q < 8; q++) {
                int2 e = s_e[j + q];
                v[q] = __int_as_float(e.y);
                f[q] = __half22float2(srcl[(size_t)e.x * 32]);
            }
#pragma unroll
            for (int q = 0; q < 8; q++) {
                a0 = fmaf(v[q], f[q].x, a0);
                a1 = fmaf(v[q], f[q].y, a1);
            }
        }
        for (; j < m; j++) {
            int2 e = s_e[j];
            float vv = __int_as_float(e.y);
            float2 f = __half22float2(srcl[(size_t)e.x * 32]);
            a0 = fmaf(vv, f.x, a0);
            a1 = fmaf(vv, f.y, a1);
        }
        __syncwarp();
    }
}

// ---------------------------------------------------------------------------
// K1: g_hh = half2( log_map(hyp_proj(x)) @ W1 ) ; zero g_counts
// ---------------------------------------------------------------------------
__global__ void k_prelude(const float* __restrict__ x, const float* __restrict__ W, int N) {
    __shared__ float Ws[64 * 64];
    for (int i = threadIdx.x; i < 64 * 64; i += blockDim.x) Ws[i] = W[i];
    __syncthreads();

    int node = (int)((blockIdx.x * blockDim.x + threadIdx.x) >> 5);
    int lane = threadIdx.x & 31;
    if (node >= N) return;
    size_t base = (size_t)node * D;

    if (lane == 0) g_counts[node] = 0;

    float a = x[base + lane], b = x[base + lane + 32];
    hproj(a, b);
    logmap(a, b);

    float o0, o1;
    matvec(a, b, Ws, lane, o0, o1);
    g_hh[(size_t)node * 32 + lane] = __floats2half2_rn(o0, o1);
}

// ---------------------------------------------------------------------------
// counting sort of edges by row
// ---------------------------------------------------------------------------
__global__ void k_hist(const int* __restrict__ rows, int E) {
    int e = (blockIdx.x * blockDim.x + threadIdx.x) * 4;
    if (e + 4 <= E) {
        int4 r = *reinterpret_cast<const int4*>(rows + e);
        atomicAdd(&g_counts[r.x], 1);
        atomicAdd(&g_counts[r.y], 1);
        atomicAdd(&g_counts[r.z], 1);
        atomicAdd(&g_counts[r.w], 1);
    } else {
        for (int k = e; k < E; k++) atomicAdd(&g_counts[rows[k]], 1);
    }
}

__global__ void k_scan_block(int N) {
    __shared__ int ws[32];
    int tid = threadIdx.x, lane = tid & 31, wid = tid >> 5;
    int i = blockIdx.x * 1024 + tid;
    int v = (i < N) ? g_counts[i] : 0;
    int x = v;
#pragma unroll
    for (int o = 1; o < 32; o <<= 1) {
        int t = __shfl_up_sync(FULLM, x, o);
        if (lane >= o) x += t;
    }
    if (lane == 31) ws[wid] = x;
    __syncthreads();
    if (wid == 0) {
        int y = ws[lane];
#pragma unroll
        for (int o = 1; o < 32; o <<= 1) {
            int t = __shfl_up_sync(FULLM, y, o);
            if (lane >= o) y += t;
        }
        ws[lane] = y;
    }
    __syncthreads();
    int wpre = (wid == 0) ? 0 : ws[wid - 1];
    if (i < N) g_off[i] = wpre + x - v;               // exclusive within block
    if (tid == 1023) g_bsum[blockIdx.x] = wpre + x;   // block total
}

__global__ void k_scan_top(int nb) {
    __shared__ int ws[32];
    int tid = threadIdx.x, lane = tid & 31, wid = tid >> 5;
    int v = (tid < nb) ? g_bsum[tid] : 0;
    int x = v;
#pragma unroll
    for (int o = 1; o < 32; o <<= 1) {
        int t = __shfl_up_sync(FULLM, x, o);
        if (lane >= o) x += t;
    }
    if (lane == 31) ws[wid] = x;
    __syncthreads();
    if (wid == 0) {
        int y = ws[lane];
#pragma unroll
        for (int o = 1; o < 32; o <<= 1) {
            int t = __shfl_up_sync(FULLM, y, o);
            if (lane >= o) y += t;
        }
        ws[lane] = y;
    }
    __syncthreads();
    int wpre = (wid == 0) ? 0 : ws[wid - 1];
    if (tid < nb) g_bscan[tid] = wpre + x - v;        // exclusive scan of block sums
}

// reorder: position = (atomic bump of block-local g_off) + block base from g_bscan
__global__ void k_reorder(const int* __restrict__ rows, const int* __restrict__ cols,
                          const float* __restrict__ vals, int E) {
    int e = (blockIdx.x * blockDim.x + threadIdx.x) * 4;
    if (e + 4 <= E) {
        int4   r = *reinterpret_cast<const int4*>(rows + e);
        int4   c = *reinterpret_cast<const int4*>(cols + e);
        float4 v = *reinterpret_cast<const float4*>(vals + e);
        int p0 = atomicAdd(&g_off[r.x], 1) + g_bscan[r.x >> 10];
        int p1 = atomicAdd(&g_off[r.y], 1) + g_bscan[r.y >> 10];
        int p2 = atomicAdd(&g_off[r.z], 1) + g_bscan[r.z >> 10];
        int p3 = atomicAdd(&g_off[r.w], 1) + g_bscan[r.w >> 10];
        g_edge[p0] = make_int2(c.x, __float_as_int(v.x));
        g_edge[p1] = make_int2(c.y, __float_as_int(v.y));
        g_edge[p2] = make_int2(c.z, __float_as_int(v.z));
        g_edge[p3] = make_int2(c.w, __float_as_int(v.w));
    } else {
        for (int k = e; k < E; k++) {
            int r = rows[k];
            int p = atomicAdd(&g_off[r], 1) + g_bscan[r >> 10];
            g_edge[p] = make_int2(cols[k], __float_as_int(vals[k]));
        }
    }
}

// ---------------------------------------------------------------------------
// K-layer1: gather(g_hh) -> epilogue+act -> residual(e0) -> g_h1,
//           then log_map + @W2 -> g_hh2
// ---------------------------------------------------------------------------
__global__ void k_layer1(const float* __restrict__ x, const float* __restrict__ bias,
                         const float* __restrict__ W2, int N) {
    __shared__ float Ws[64 * 64];
    __shared__ int2  s_e[8][32];
    for (int i = threadIdx.x; i < 64 * 64; i += blockDim.x) Ws[i] = W2[i];
    __syncthreads();

    int wid  = threadIdx.x >> 5;
    int node = (int)(blockIdx.x * 8 + wid);
    int lane = threadIdx.x & 31;
    if (node >= N) return;
    size_t base = (size_t)node * D;

    float oa, ob;
    gather_row(g_hh, s_e[wid], node, lane, oa, ob);

    // bias in hyperbolic space
    float ba = bias[lane], bb = bias[lane + 32];
    expmap(ba, bb); hproj(ba, bb);

    expmap(oa, ob); hproj(oa, ob);
    mobius(oa, ob, ba, bb); hproj(oa, ob);
    // activation: hyp_proj(exp_map(tanh(log_map(out))))
    logmap(oa, ob);
    oa = tanhf(oa); ob = tanhf(ob);
    expmap(oa, ob); hproj(oa, ob);

    // residual with e0 = hyp_proj(x)
    float ea = x[base + lane], eb = x[base + lane + 32];
    hproj(ea, eb);
    mobius(oa, ob, ea, eb); hproj(oa, ob);

    g_h1[base + lane] = oa;
    g_h1[base + lane + 32] = ob;

    // layer-2 prelude
    logmap(oa, ob);
    float o0, o1;
    matvec(oa, ob, Ws, lane, o0, o1);
    g_hh2[(size_t)node * 32 + lane] = __floats2half2_rn(o0, o1);
}

// ---------------------------------------------------------------------------
// K-layer2: gather(g_hh2) -> epilogue (no act) -> residual(g_h1) -> out
// ---------------------------------------------------------------------------
__global__ void k_layer2(const float* __restrict__ bias, float* __restrict__ out, int N) {
    __shared__ int2 s_e[8][32];
    int wid  = threadIdx.x >> 5;
    int node = (int)(blockIdx.x * 8 + wid);
    int lane = threadIdx.x & 31;
    if (node >= N) return;
    size_t base = (size_t)node * D;

    float oa, ob;
    gather_row(g_hh2, s_e[wid], node, lane, oa, ob);

    float ba = bias[lane], bb = bias[lane + 32];
    expmap(ba, bb); hproj(ba, bb);

    expmap(oa, ob); hproj(oa, ob);
    mobius(oa, ob, ba, bb); hproj(oa, ob);

    float ra = g_h1[base + lane], rb = g_h1[base + lane + 32];
    mobius(oa, ob, ra, rb); hproj(oa, ob);

    out[base + lane] = oa;
    out[base + lane + 32] = ob;
}

// ---------------------------------------------------------------------------
extern "C" void kernel_launch(void* const* d_in, const int* in_sizes, int n_in,
                              void* d_out, int out_size) {
    const float* x    = (const float*)d_in[0];
    const float* vals = (const float*)d_in[1];
    const float* W1   = (const float*)d_in[2];
    const float* b1   = (const float*)d_in[3];
    const float* W2   = (const float*)d_in[4];
    const float* b2   = (const float*)d_in[5];
    const int*   rows = (const int*)d_in[6];
    const int*   cols = (const int*)d_in[7];

    int N = in_sizes[0] / D;
    int E = in_sizes[1];

    int nodeBlocks  = (N + 7) / 8;            // 8 warps (nodes) per 256-thread block
    int edge4Blocks = (E / 4 + 256) / 256;    // 4 edges per thread (covers tail)
    int nb          = (N + 1023) / 1024;      // scan blocks (<= 1024)

    k_prelude   <<<nodeBlocks, 256>>>(x, W1, N);
    k_hist      <<<edge4Blocks, 256>>>(rows, E);
    k_scan_block<<<nb, 1024>>>(N);
    k_scan_top  <<<1, 1024>>>(nb);
    k_reorder   <<<edge4Blocks, 256>>>(rows, cols, vals, E);
    k_layer1    <<<nodeBlocks, 256>>>(x, b1, W2, N);
    k_layer2    <<<nodeBlocks, 256>>>(b2, (float*)d_out, N);
}

// round 13
// speedup vs baseline: 1.1285x; 1.0078x over previous
#include <cuda_runtime.h>
#include <cuda_fp16.h>
#include <math.h>

// ---------------------------------------------------------------------------
// HyperKA 2-layer hyperbolic GCN.  N<=131072 nodes, D=64, E<=4M edges.
// Counting-sort edges by row each launch, then atomic-free warp-per-row
// gather with fp16 feature rows.  Gather processes TWO edges per load
// instruction: 16 lanes x 8B per row (LDG.64), edges staged in smem.
// All math fp32.
// ---------------------------------------------------------------------------

#define MAXN 131072
#define MAXE 4194304
#define D 64
#define FULLM 0xffffffffu

__device__ __half2 g_hh [(size_t)MAXN * 32];  // layer-1 SpMM input (half2 k = dims (k, k+32))
__device__ __half2 g_hh2[(size_t)MAXN * 32];  // layer-2 SpMM input
__device__ float   g_h1 [(size_t)MAXN * D];   // layer-1 output (residual), fp32
__device__ int     g_counts[MAXN];
__device__ int     g_off   [MAXN];            // block-local excl. scan; cursor during reorder
__device__ int     g_bsum [1024];
__device__ int     g_bscan[1024];             // exclusive scan of 1024-blocks
__device__ int2    g_edge [MAXE];             // .x = col, .y = val bits

#define EPS2    1e-12f        // EPS*EPS
#define PEPS    1e-5f         // PROJ_EPS
#define DEN_EPS 1e-6f

// ---- warp helpers (warp == one node, lane l owns dims l and l+32) ----------

__device__ __forceinline__ float wsum(float v) {
#pragma unroll
    for (int o = 16; o; o >>= 1) v += __shfl_xor_sync(FULLM, v, o);
    return v;
}

__device__ __forceinline__ void hproj(float& a, float& b) {
    float ss = wsum(a * a + b * b);
    float n  = sqrtf(fmaxf(ss, EPS2));
    float s  = fminf((1.0f - PEPS) / n, 1.0f);
    a *= s; b *= s;
}

__device__ __forceinline__ void expmap(float& a, float& b) {
    float ss = wsum(a * a + b * b);
    float n  = sqrtf(fmaxf(ss, EPS2));
    float s  = tanhf(n) / n;
    a *= s; b *= s;
}

__device__ __forceinline__ void logmap(float& a, float& b) {
    float ss = wsum(a * a + b * b);
    float n  = sqrtf(fmaxf(ss, EPS2));
    float s  = atanhf(fminf(n, 1.0f - PEPS)) / n;
    a *= s; b *= s;
}

// x <- mobius_add(x, y)
__device__ __forceinline__ void mobius(float& xa, float& xb, float ya, float yb) {
    float x2 = wsum(xa * xa + xb * xb);
    float y2 = wsum(ya * ya + yb * yb);
    float xy = wsum(xa * ya + xb * yb);
    float c1  = 1.0f + 2.0f * xy + y2;
    float c2  = 1.0f - x2;
    float den = fmaxf(1.0f + 2.0f * xy + x2 * y2, DEN_EPS);
    float inv = 1.0f / den;
    xa = (c1 * xa + c2 * ya) * inv;
    xb = (c1 * xb + c2 * yb) * inv;
}

// o = v @ W  (W in smem, row-major 64x64)
__device__ __forceinline__ void matvec(float a, float b, const float* Ws, int lane,
                                       float& o0, float& o1) {
    o0 = 0.0f; o1 = 0.0f;
#pragma unroll
    for (int k = 0; k < 32; k++) {
        float t = __shfl_sync(FULLM, a, k);
        o0 = fmaf(t, Ws[k * 64 + lane],      o0);
        o1 = fmaf(t, Ws[k * 64 + lane + 32], o1);
    }
#pragma unroll
    for (int k = 0; k < 32; k++) {
        float t = __shfl_sync(FULLM, b, k);
        o0 = fmaf(t, Ws[(k + 32) * 64 + lane],      o0);
        o1 = fmaf(t, Ws[(k + 32) * 64 + lane + 32], o1);
    }
}

__device__ __forceinline__ float2 h2f(unsigned int bits) {
    __half2 h = *reinterpret_cast<__half2*>(&bits);
    return __half22float2(h);
}

// warp-per-row gather, two edges per load instruction.
// Lanes 0-15 handle even edge of each pair, lanes 16-31 the odd edge.
// Lane (h = lane&15) loads uint2 = half2 indices {2h, 2h+1} of the row,
// i.e. dims (2h, 2h+32, 2h+1, 2h+33).  Final xor-16 reduce + permute
// restores the (lane, lane+32) layout.
__device__ __forceinline__ void gather_row(const __half2* __restrict__ src,
                                           int2* __restrict__ s_e,   // per-warp [32]
                                           int node, int lane,
                                           float& oa, float& ob) {
    int deg   = g_counts[node];
    // post-reorder g_off[node] = local_off + deg; global start = +bscan - deg
    int start = g_off[node] + g_bscan[node >> 10] - deg;
    int h     = lane & 15;
    int side  = lane >> 4;
    float a0 = 0.0f, a1 = 0.0f, a2 = 0.0f, a3 = 0.0f;
    const uint2* srch = reinterpret_cast<const uint2*>(src) + h;

    for (int j0 = 0; j0 < deg; j0 += 32) {
        int rem = deg - j0;
        int m = rem < 32 ? rem : 32;
        if (lane < m) s_e[lane] = g_edge[start + j0 + lane];
        __syncwarp();
        int j = 0;
        // 8 pairs = 16 edges per iteration, 8 LDG.64 in flight
        for (; j + 16 <= m; j += 16) {
            float v[8]; uint2 u[8];
#pragma unroll
            for (int q = 0; q < 8; q++) {
                int2 e = s_e[j + 2 * q + side];
                v[q] = __int_as_float(e.y);
                u[q] = srch[(size_t)e.x * 16];
            }
#pragma unroll
            for (int q = 0; q < 8; q++) {
                float2 f0 = h2f(u[q].x);
                float2 f1 = h2f(u[q].y);
                a0 = fmaf(v[q], f0.x, a0);
                a1 = fmaf(v[q], f0.y, a1);
                a2 = fmaf(v[q], f1.x, a2);
                a3 = fmaf(v[q], f1.y, a3);
            }
        }
        // leftover pairs
        for (; j + 2 <= m; j += 2) {
            int2 e = s_e[j + side];
            float v = __int_as_float(e.y);
            uint2 u = srch[(size_t)e.x * 16];
            float2 f0 = h2f(u.x);
            float2 f1 = h2f(u.y);
            a0 = fmaf(v, f0.x, a0);
            a1 = fmaf(v, f0.y, a1);
            a2 = fmaf(v, f1.x, a2);
            a3 = fmaf(v, f1.y, a3);
        }
        // odd tail edge: side-1 lanes contribute 0 (same address, harmless)
        if (j < m) {
            int2 e = s_e[j];
            float v = side ? 0.0f : __int_as_float(e.y);
            uint2 u = srch[(size_t)e.x * 16];
            float2 f0 = h2f(u.x);
            float2 f1 = h2f(u.y);
            a0 = fmaf(v, f0.x, a0);
            a1 = fmaf(v, f0.y, a1);
            a2 = fmaf(v, f1.x, a2);
            a3 = fmaf(v, f1.y, a3);
        }
        __syncwarp();
    }

    // combine the two half-warps
    a0 += __shfl_xor_sync(FULLM, a0, 16);
    a1 += __shfl_xor_sync(FULLM, a1, 16);
    a2 += __shfl_xor_sync(FULLM, a2, 16);
    a3 += __shfl_xor_sync(FULLM, a3, 16);

    // permute to (lane, lane+32) layout: dims of lane l live in lane l>>1
    int s = lane >> 1;
    float f0 = __shfl_sync(FULLM, a0, s);
    float f1 = __shfl_sync(FULLM, a1, s);
    float f2 = __shfl_sync(FULLM, a2, s);
    float f3 = __shfl_sync(FULLM, a3, s);
    if (lane & 1) { oa = f2; ob = f3; }
    else          { oa = f0; ob = f1; }
}

// ---------------------------------------------------------------------------
// K1: g_hh = half2( log_map(hyp_proj(x)) @ W1 ) ; zero g_counts
// ---------------------------------------------------------------------------
__global__ void k_prelude(const float* __restrict__ x, const float* __restrict__ W, int N) {
    __shared__ float Ws[64 * 64];
    for (int i = threadIdx.x; i < 64 * 64; i += blockDim.x) Ws[i] = W[i];
    __syncthreads();

    int node = (int)((blockIdx.x * blockDim.x + threadIdx.x) >> 5);
    int lane = threadIdx.x & 31;
    if (node >= N) return;
    size_t base = (size_t)node * D;

    if (lane == 0) g_counts[node] = 0;

    float a = x[base + lane], b = x[base + lane + 32];
    hproj(a, b);
    logmap(a, b);

    float o0, o1;
    matvec(a, b, Ws, lane, o0, o1);
    g_hh[(size_t)node * 32 + lane] = __floats2half2_rn(o0, o1);
}

// ---------------------------------------------------------------------------
// counting sort of edges by row
// ---------------------------------------------------------------------------
__global__ void k_hist(const int* __restrict__ rows, int E) {
    int e = (blockIdx.x * blockDim.x + threadIdx.x) * 4;
    if (e + 4 <= E) {
        int4 r = *reinterpret_cast<const int4*>(rows + e);
        atomicAdd(&g_counts[r.x], 1);
        atomicAdd(&g_counts[r.y], 1);
        atomicAdd(&g_counts[r.z], 1);
        atomicAdd(&g_counts[r.w], 1);
    } else {
        for (int k = e; k < E; k++) atomicAdd(&g_counts[rows[k]], 1);
    }
}

__global__ void k_scan_block(int N) {
    __shared__ int ws[32];
    int tid = threadIdx.x, lane = tid & 31, wid = tid >> 5;
    int i = blockIdx.x * 1024 + tid;
    int v = (i < N) ? g_counts[i] : 0;
    int x = v;
#pragma unroll
    for (int o = 1; o < 32; o <<= 1) {
        int t = __shfl_up_sync(FULLM, x, o);
        if (lane >= o) x += t;
    }
    if (lane == 31) ws[wid] = x;
    __syncthreads();
    if (wid == 0) {
        int y = ws[lane];
#pragma unroll
        for (int o = 1; o < 32; o <<= 1) {
            int t = __shfl_up_sync(FULLM, y, o);
            if (lane >= o) y += t;
        }
        ws[lane] = y;
    }
    __syncthreads();
    int wpre = (wid == 0) ? 0 : ws[wid - 1];
    if (i < N) g_off[i] = wpre + x - v;               // exclusive within block
    if (tid == 1023) g_bsum[blockIdx.x] = wpre + x;   // block total
}

__global__ void k_scan_top(int nb) {
    __shared__ int ws[32];
    int tid = threadIdx.x, lane = tid & 31, wid = tid >> 5;
    int v = (tid < nb) ? g_bsum[tid] : 0;
    int x = v;
#pragma unroll
    for (int o = 1; o < 32; o <<= 1) {
        int t = __shfl_up_sync(FULLM, x, o);
        if (lane >= o) x += t;
    }
    if (lane == 31) ws[wid] = x;
    __syncthreads();
    if (wid == 0) {
        int y = ws[lane];
#pragma unroll
        for (int o = 1; o < 32; o <<= 1) {
            int t = __shfl_up_sync(FULLM, y, o);
            if (lane >= o) y += t;
        }
        ws[lane] = y;
    }
    __syncthreads();
    int wpre = (wid == 0) ? 0 : ws[wid - 1];
    if (tid < nb) g_bscan[tid] = wpre + x - v;        // exclusive scan of block sums
}

// reorder: position = (atomic bump of block-local g_off) + block base from g_bscan
__global__ void k_reorder(const int* __restrict__ rows, const int* __restrict__ cols,
                          const float* __restrict__ vals, int E) {
    int e = (blockIdx.x * blockDim.x + threadIdx.x) * 4;
    if (e + 4 <= E) {
        int4   r = *reinterpret_cast<const int4*>(rows + e);
        int4   c = *reinterpret_cast<const int4*>(cols + e);
        float4 v = *reinterpret_cast<const float4*>(vals + e);
        int p0 = atomicAdd(&g_off[r.x], 1) + g_bscan[r.x >> 10];
        int p1 = atomicAdd(&g_off[r.y], 1) + g_bscan[r.y >> 10];
        int p2 = atomicAdd(&g_off[r.z], 1) + g_bscan[r.z >> 10];
        int p3 = atomicAdd(&g_off[r.w], 1) + g_bscan[r.w >> 10];
        g_edge[p0] = make_int2(c.x, __float_as_int(v.x));
        g_edge[p1] = make_int2(c.y, __float_as_int(v.y));
        g_edge[p2] = make_int2(c.z, __float_as_int(v.z));
        g_edge[p3] = make_int2(c.w, __float_as_int(v.w));
    } else {
        for (int k = e; k < E; k++) {
            int r = rows[k];
            int p = atomicAdd(&g_off[r], 1) + g_bscan[r >> 10];
            g_edge[p] = make_int2(cols[k], __float_as_int(vals[k]));
        }
    }
}

// ---------------------------------------------------------------------------
// K-layer1: gather(g_hh) -> epilogue+act -> residual(e0) -> g_h1,
//           then log_map + @W2 -> g_hh2
// ---------------------------------------------------------------------------
__global__ void k_layer1(const float* __restrict__ x, const float* __restrict__ bias,
                         const float* __restrict__ W2, int N) {
    __shared__ float Ws[64 * 64];
    __shared__ int2  s_e[8][32];
    for (int i = threadIdx.x; i < 64 * 64; i += blockDim.x) Ws[i] = W2[i];
    __syncthreads();

    int wid  = threadIdx.x >> 5;
    int node = (int)(blockIdx.x * 8 + wid);
    int lane = threadIdx.x & 31;
    if (node >= N) return;
    size_t base = (size_t)node * D;

    float oa, ob;
    gather_row(g_hh, s_e[wid], node, lane, oa, ob);

    // bias in hyperbolic space
    float ba = bias[lane], bb = bias[lane + 32];
    expmap(ba, bb); hproj(ba, bb);

    expmap(oa, ob); hproj(oa, ob);
    mobius(oa, ob, ba, bb); hproj(oa, ob);
    // activation: hyp_proj(exp_map(tanh(log_map(out))))
    logmap(oa, ob);
    oa = tanhf(oa); ob = tanhf(ob);
    expmap(oa, ob); hproj(oa, ob);

    // residual with e0 = hyp_proj(x)
    float ea = x[base + lane], eb = x[base + lane + 32];
    hproj(ea, eb);
    mobius(oa, ob, ea, eb); hproj(oa, ob);

    g_h1[base + lane] = oa;
    g_h1[base + lane + 32] = ob;

    // layer-2 prelude
    logmap(oa, ob);
    float o0, o1;
    matvec(oa, ob, Ws, lane, o0, o1);
    g_hh2[(size_t)node * 32 + lane] = __floats2half2_rn(o0, o1);
}

// ---------------------------------------------------------------------------
// K-layer2: gather(g_hh2) -> epilogue (no act) -> residual(g_h1) -> out
// ---------------------------------------------------------------------------
__global__ void k_layer2(const float* __restrict__ bias, float* __restrict__ out, int N) {
    __shared__ int2 s_e[8][32];
    int wid  = threadIdx.x >> 5;
    int node = (int)(blockIdx.x * 8 + wid);
    int lane = threadIdx.x & 31;
    if (node >= N) return;
    size_t base = (size_t)node * D;

    float oa, ob;
    gather_row(g_hh2, s_e[wid], node, lane, oa, ob);

    float ba = bias[lane], bb = bias[lane + 32];
    expmap(ba, bb); hproj(ba, bb);

    expmap(oa, ob); hproj(oa, ob);
    mobius(oa, ob, ba, bb); hproj(oa, ob);

    float ra = g_h1[base + lane], rb = g_h1[base + lane + 32];
    mobius(oa, ob, ra, rb); hproj(oa, ob);

    out[base + lane] = oa;
    out[base + lane + 32] = ob;
}

// ---------------------------------------------------------------------------
extern "C" void kernel_launch(void* const* d_in, const int* in_sizes, int n_in,
                              void* d_out, int out_size) {
    const float* x    = (const float*)d_in[0];
    const float* vals = (const float*)d_in[1];
    const float* W1   = (const float*)d_in[2];
    const float* b1   = (const float*)d_in[3];
    const float* W2   = (const float*)d_in[4];
    const float* b2   = (const float*)d_in[5];
    const int*   rows = (const int*)d_in[6];
    const int*   cols = (const int*)d_in[7];

    int N = in_sizes[0] / D;
    int E = in_sizes[1];

    int nodeBlocks  = (N + 7) / 8;            // 8 warps (nodes) per 256-thread block
    int edge4Blocks = (E / 4 + 256) / 256;    // 4 edges per thread (covers tail)
    int nb          = (N + 1023) / 1024;      // scan blocks (<= 1024)

    k_prelude   <<<nodeBlocks, 256>>>(x, W1, N);
    k_hist      <<<edge4Blocks, 256>>>(rows, E);
    k_scan_block<<<nb, 1024>>>(N);
    k_scan_top  <<<1, 1024>>>(nb);
    k_reorder   <<<edge4Blocks, 256>>>(rows, cols, vals, E);
    k_layer1    <<<nodeBlocks, 256>>>(x, b1, W2, N);
    k_layer2    <<<nodeBlocks, 256>>>(b2, (float*)d_out, N);
}